// round 6
// baseline (speedup 1.0000x reference)
#include <cuda_runtime.h>
#include <cstdint>

// out[r, c] = filt[r] * x[r, c]
// x: [8192, 4096] fp32, filt: [8192] fp32, out: [8192, 4096] fp32
// Pure HBM-bound streaming op. float4 vectorization, row via shift (M/4 = 1024).
// Compile-time-exact decomposition: 2048 blocks * 256 thr * 16 iters = 8,388,608 float4.

static constexpr int SIZE = 8192;   // rows
static constexpr int M    = 4096;   // cols
static constexpr int M4   = M / 4;          // 1024 float4 per row
static constexpr int M4_SHIFT = 10;         // log2(M4)
static constexpr int TOTAL4   = SIZE * M4;  // 8,388,608
static constexpr int THREADS  = 256;
static constexpr int BLOCKS   = 2048;
static constexpr int ITERS    = TOTAL4 / (THREADS * BLOCKS);  // 16, exact
static constexpr int STRIDE   = THREADS * BLOCKS;             // 524,288

__global__ void __launch_bounds__(THREADS) diag_filter_kernel(
        const float4* __restrict__ x,
        const float* __restrict__ filt,
        float4* __restrict__ out) {
    int idx = blockIdx.x * THREADS + threadIdx.x;
    #pragma unroll
    for (int it = 0; it < ITERS; ++it) {
        int i = idx + it * STRIDE;
        int row = i >> M4_SHIFT;
        float f = __ldg(&filt[row]);
        float4 v = x[i];
        v.x *= f; v.y *= f; v.z *= f; v.w *= f;
        out[i] = v;
    }
}

extern "C" void kernel_launch(void* const* d_in, const int* in_sizes, int n_in,
                              void* d_out, int out_size) {
    const float4* x    = (const float4*)d_in[0];
    const float*  filt = (const float*)d_in[1];
    float4*       out  = (float4*)d_out;
    diag_filter_kernel<<<BLOCKS, THREADS>>>(x, filt, out);
}